// round 12
// baseline (speedup 1.0000x reference)
#include <cuda_runtime.h>

// out[i*2+0] = sum of edge_attr[e] for edges with edgeij_pair[0][e] == i
// out[i*2+1] = vertex_attr[i*2+1]
//
// zero_out (primary, fires launch_dependents immediately) || fused_scatter
// (PDL secondary): scatter blocks are scheduled while zero_out runs, issue
// edge/vattr loads right away (disjoint buffers), then griddepcontrol.wait
// before touching `out`. First edge_blocks do the 2-edge/thread atomic
// scatter; trailing copy blocks write the y column in the drain tail.

__global__ void zero_out_kernel(float4* __restrict__ out, int n_quads) {
    // Let the dependent (scatter) grid start scheduling NOW.
    asm volatile("griddepcontrol.launch_dependents;" ::: "memory");
    int i = blockIdx.x * blockDim.x + threadIdx.x;
    if (i < n_quads)
        out[i] = make_float4(0.f, 0.f, 0.f, 0.f);
}

__global__ void zero_out_tail_kernel(float* __restrict__ out,
                                     int start, int n_elems) {
    asm volatile("griddepcontrol.launch_dependents;" ::: "memory");
    int i = start + blockIdx.x * blockDim.x + threadIdx.x;
    if (i < n_elems)
        out[i] = 0.f;
}

__global__ void __launch_bounds__(256) fused_scatter_kernel(
        const int2* __restrict__ idx2,
        const float2* __restrict__ val2,
        const float* __restrict__ vattr,
        float* __restrict__ out,
        int n_pairs, int n_vertices, int edge_blocks) {
    int b = blockIdx.x;
    if (b < edge_blocks) {
        int t = b * blockDim.x + threadIdx.x;
        int2   vi;
        float2 va;
        bool active = (t < n_pairs);
        if (active) {
            vi = idx2[t];
            va = val2[t];
        }
        // Wait for zero_out's memory to be visible before the first atomic.
        asm volatile("griddepcontrol.wait;" ::: "memory");
        if (active) {
            atomicAdd(out + 2 * vi.x, va.x);
            atomicAdd(out + 2 * vi.y, va.y);
        }
    } else {
        int i = (b - edge_blocks) * blockDim.x + threadIdx.x;
        float y = 0.f;
        bool active = (i < n_vertices);
        if (active)
            y = vattr[2 * i + 1];
        asm volatile("griddepcontrol.wait;" ::: "memory");
        if (active)
            out[2 * i + 1] = y;
    }
}

__global__ void scatter_tail_kernel(const int* __restrict__ idx,
                                    const float* __restrict__ val,
                                    float* __restrict__ out,
                                    int start, int n_edges) {
    int e = start + blockIdx.x * blockDim.x + threadIdx.x;
    if (e < n_edges)
        atomicAdd(out + 2 * idx[e], val[e]);
}

extern "C" void kernel_launch(void* const* d_in, const int* in_sizes, int n_in,
                              void* d_out, int out_size) {
    // metadata order: vertex_attr [N,2] f32, edgeij_pair [2,E] i32,
    //                 edge_attr [E,1] f32, g [1,1] f32, batch [N] i32
    const float* vattr = (const float*)d_in[0];
    const int*   eij   = (const int*)d_in[1];
    const float* eattr = (const float*)d_in[2];
    float* out = (float*)d_out;

    int n_vertices = in_sizes[0] / 2;
    int n_edges    = in_sizes[2];
    const int* src_idx = eij; // row 0 of [2, E]

    const int threads = 256;

    // Zero both columns of out (y column overwritten by the copy blocks).
    {
        int n_elems = 2 * n_vertices;
        int n_quads = n_elems / 4;
        int blocks = (n_quads + threads - 1) / threads;
        if (blocks > 0)
            zero_out_kernel<<<blocks, threads>>>((float4*)out, n_quads);
        int done = n_quads * 4;
        if (done < n_elems)
            zero_out_tail_kernel<<<1, 32>>>(out, done, n_elems);
    }

    // Fused scatter + y-copy, PDL-overlapped with the zero kernel.
    {
        int n_pairs = n_edges / 2;
        int edge_blocks = (n_pairs + threads - 1) / threads;
        int copy_blocks = (n_vertices + threads - 1) / threads;
        int total = edge_blocks + copy_blocks;
        if (total > 0) {
            cudaLaunchConfig_t cfg = {};
            cfg.gridDim = dim3(total, 1, 1);
            cfg.blockDim = dim3(threads, 1, 1);
            cfg.dynamicSmemBytes = 0;
            cfg.stream = 0;
            cudaLaunchAttribute attrs[1];
            attrs[0].id = cudaLaunchAttributeProgrammaticStreamSerialization;
            attrs[0].val.programmaticStreamSerializationAllowed = 1;
            cfg.attrs = attrs;
            cfg.numAttrs = 1;
            cudaLaunchKernelEx(&cfg, fused_scatter_kernel,
                               (const int2*)src_idx, (const float2*)eattr,
                               vattr, out, n_pairs, n_vertices, edge_blocks);
        }
        int done = n_pairs * 2;
        if (done < n_edges)
            scatter_tail_kernel<<<1, 32>>>(src_idx, eattr, out,
                                           done, n_edges);
    }
}

// round 13
// speedup vs baseline: 1.0023x; 1.0023x over previous
#include <cuda_runtime.h>

// out[i*2+0] = sum of edge_attr[e] for edges with edgeij_pair[0][e] == i
// out[i*2+1] = vertex_attr[i*2+1]
//
// Final configuration (best measured, R11 = 164.0us):
//   zero_out (primary) || fused_scatter (PDL secondary, implicit trigger):
//   - fused_scatter blocks issue edge/vattr loads immediately (disjoint
//     buffers), then griddepcontrol.wait before touching `out`.
//   - first edge_blocks: 2-edge/thread atomic scatter (LTS-RMW-floor config)
//   - trailing copy blocks: y-column copy, rides the atomic drain tail.

__global__ void zero_out_kernel(float4* __restrict__ out, int n_quads) {
    int i = blockIdx.x * blockDim.x + threadIdx.x;
    if (i < n_quads)
        out[i] = make_float4(0.f, 0.f, 0.f, 0.f);
}

__global__ void zero_out_tail_kernel(float* __restrict__ out,
                                     int start, int n_elems) {
    int i = start + blockIdx.x * blockDim.x + threadIdx.x;
    if (i < n_elems)
        out[i] = 0.f;
}

__global__ void __launch_bounds__(256) fused_scatter_kernel(
        const int2* __restrict__ idx2,
        const float2* __restrict__ val2,
        const float* __restrict__ vattr,
        float* __restrict__ out,
        int n_pairs, int n_vertices, int edge_blocks) {
    int b = blockIdx.x;
    if (b < edge_blocks) {
        int t = b * blockDim.x + threadIdx.x;
        int2   vi;
        float2 va;
        bool active = (t < n_pairs);
        if (active) {
            vi = idx2[t];
            va = val2[t];
        }
        // Wait for zero_out's memory to be visible before the first atomic.
        asm volatile("griddepcontrol.wait;" ::: "memory");
        if (active) {
            atomicAdd(out + 2 * vi.x, va.x);
            atomicAdd(out + 2 * vi.y, va.y);
        }
    } else {
        int i = (b - edge_blocks) * blockDim.x + threadIdx.x;
        float y = 0.f;
        bool active = (i < n_vertices);
        if (active)
            y = vattr[2 * i + 1];
        asm volatile("griddepcontrol.wait;" ::: "memory");
        if (active)
            out[2 * i + 1] = y;
    }
}

__global__ void scatter_tail_kernel(const int* __restrict__ idx,
                                    const float* __restrict__ val,
                                    float* __restrict__ out,
                                    int start, int n_edges) {
    int e = start + blockIdx.x * blockDim.x + threadIdx.x;
    if (e < n_edges)
        atomicAdd(out + 2 * idx[e], val[e]);
}

extern "C" void kernel_launch(void* const* d_in, const int* in_sizes, int n_in,
                              void* d_out, int out_size) {
    // metadata order: vertex_attr [N,2] f32, edgeij_pair [2,E] i32,
    //                 edge_attr [E,1] f32, g [1,1] f32, batch [N] i32
    const float* vattr = (const float*)d_in[0];
    const int*   eij   = (const int*)d_in[1];
    const float* eattr = (const float*)d_in[2];
    float* out = (float*)d_out;

    int n_vertices = in_sizes[0] / 2;
    int n_edges    = in_sizes[2];
    const int* src_idx = eij; // row 0 of [2, E]

    const int threads = 256;

    // Zero both columns of out (y column overwritten by the copy blocks).
    {
        int n_elems = 2 * n_vertices;
        int n_quads = n_elems / 4;
        int blocks = (n_quads + threads - 1) / threads;
        if (blocks > 0)
            zero_out_kernel<<<blocks, threads>>>((float4*)out, n_quads);
        int done = n_quads * 4;
        if (done < n_elems)
            zero_out_tail_kernel<<<1, 32>>>(out, done, n_elems);
    }

    // Fused scatter + y-copy, PDL-overlapped with the zero kernel.
    {
        int n_pairs = n_edges / 2;
        int edge_blocks = (n_pairs + threads - 1) / threads;
        int copy_blocks = (n_vertices + threads - 1) / threads;
        int total = edge_blocks + copy_blocks;
        if (total > 0) {
            cudaLaunchConfig_t cfg = {};
            cfg.gridDim = dim3(total, 1, 1);
            cfg.blockDim = dim3(threads, 1, 1);
            cfg.dynamicSmemBytes = 0;
            cfg.stream = 0;
            cudaLaunchAttribute attrs[1];
            attrs[0].id = cudaLaunchAttributeProgrammaticStreamSerialization;
            attrs[0].val.programmaticStreamSerializationAllowed = 1;
            cfg.attrs = attrs;
            cfg.numAttrs = 1;
            cudaLaunchKernelEx(&cfg, fused_scatter_kernel,
                               (const int2*)src_idx, (const float2*)eattr,
                               vattr, out, n_pairs, n_vertices, edge_blocks);
        }
        int done = n_pairs * 2;
        if (done < n_edges)
            scatter_tail_kernel<<<1, 32>>>(src_idx, eattr, out,
                                           done, n_edges);
    }
}